// round 7
// baseline (speedup 1.0000x reference)
#include <cuda_runtime.h>
#include <cstdint>

// Problem constants
#define Bb 2
#define Tt 4
#define Nn 1024
#define Fin 256
#define Hh 8
#define Dd 128
#define BTH (Bb*Tt*Hh)          // 64
#define SLOPE 0.2f

// Scratch (device globals; no runtime allocation allowed)
__device__ float g_ht[(size_t)BTH * Nn * Dd];     // 32 MB, [bth][n][d]
__device__ float g_part[(size_t)BTH * Nn * Dd];   // 32 MB partial outputs
__device__ float g_Es [BTH * Nn];                 // exp(src)
__device__ float g_Es2[BTH * Nn];                 // exp(0.2*src)
__device__ float g_Et [BTH * Nn];                 // exp(tgt)
__device__ float g_Et2[BTH * Nn];                 // exp(0.2*tgt)
__device__ float g_Zinv[BTH * Nn];                // 1 / row-sum of weights

// ---- packed f32x2 helpers (family-wide PTX, sm_100+) ----------------------
__device__ __forceinline__ void ffma2(unsigned long long& d,
                                      unsigned long long a,
                                      unsigned long long b) {
    asm("fma.rn.f32x2 %0, %1, %2, %0;" : "+l"(d) : "l"(a), "l"(b));
}
__device__ __forceinline__ unsigned long long pk2(float lo, float hi) {
    unsigned long long r;
    asm("mov.b64 %0, {%1, %2};" : "=l"(r) : "f"(lo), "f"(hi));
    return r;
}
__device__ __forceinline__ unsigned long long dup2(float v) {
    unsigned long long r;
    asm("mov.b64 %0, {%1, %1};" : "=l"(r) : "f"(v));
    return r;
}
__device__ __forceinline__ float2 unpk2(unsigned long long u) {
    union { unsigned long long u; float2 f; } c; c.u = u; return c.f;
}

// ---------------------------------------------------------------------------
// Kernel 1: ht = h @ W, written as [bt][head][n][d]
// grid (8 heads, 8 row-tiles, 8 bt), 256 threads, 128x128x16 tiles
// ---------------------------------------------------------------------------
__global__ void __launch_bounds__(256, 2)
k_gemm_ht(const float* __restrict__ h, const float* __restrict__ W) {
    __shared__ float As[16][132];   // As[k][row]
    __shared__ float Bs[16][128];   // Bs[k][col]

    const int bt   = blockIdx.z;
    const int head = blockIdx.x;
    const int row0 = blockIdx.y * 128;
    const int col0 = head * 128;

    const float* A = h + (size_t)bt * Nn * Fin;   // [1024][256]
    const int tid = threadIdx.x;
    const int tx = tid & 15, ty = tid >> 4;

    unsigned long long acc[8][4];
#pragma unroll
    for (int i = 0; i < 8; i++)
#pragma unroll
        for (int j = 0; j < 4; j++) acc[i][j] = 0ull;

    for (int kt = 0; kt < Fin; kt += 16) {
#pragma unroll
        for (int q = tid; q < 512; q += 256) {
            int r = q >> 2, c4 = q & 3;
            float4 v = *(const float4*)(A + (size_t)(row0 + r) * Fin + kt + c4 * 4);
            As[c4 * 4 + 0][r] = v.x;
            As[c4 * 4 + 1][r] = v.y;
            As[c4 * 4 + 2][r] = v.z;
            As[c4 * 4 + 3][r] = v.w;
        }
#pragma unroll
        for (int q = tid; q < 512; q += 256) {
            int r = q >> 5, c4 = q & 31;
            *(float4*)&Bs[r][c4 * 4] =
                *(const float4*)(W + (size_t)(kt + r) * (Hh * Dd) + col0 + c4 * 4);
        }
        __syncthreads();
#pragma unroll
        for (int k = 0; k < 16; k++) {
            float a8[8], b8[8];
            *(float4*)(a8)     = *(const float4*)&As[k][ty * 8];
            *(float4*)(a8 + 4) = *(const float4*)&As[k][ty * 8 + 4];
            *(float4*)(b8)     = *(const float4*)&Bs[k][tx * 8];
            *(float4*)(b8 + 4) = *(const float4*)&Bs[k][tx * 8 + 4];
            unsigned long long bd[4];
#pragma unroll
            for (int j = 0; j < 4; j++) bd[j] = pk2(b8[2 * j], b8[2 * j + 1]);
#pragma unroll
            for (int i = 0; i < 8; i++) {
                unsigned long long ad = dup2(a8[i]);
#pragma unroll
                for (int j = 0; j < 4; j++) ffma2(acc[i][j], ad, bd[j]);
            }
        }
        __syncthreads();
    }

    float* outp = g_ht + (size_t)(bt * Hh + head) * Nn * Dd;
#pragma unroll
    for (int i = 0; i < 8; i++) {
        int r = row0 + ty * 8 + i;
#pragma unroll
        for (int j = 0; j < 4; j += 2) {
            float2 lo = unpk2(acc[i][j]), hi = unpk2(acc[i][j + 1]);
            float4 v = make_float4(lo.x, lo.y, hi.x, hi.y);
            *(float4*)(outp + (size_t)r * Dd + tx * 8 + j * 2) = v;
        }
    }
}

// ---------------------------------------------------------------------------
// Kernel 2: per-node src/tgt dot products and the 4 exps. One warp per node.
// ---------------------------------------------------------------------------
__global__ void k_edge(const float* __restrict__ a) {
    int w = (blockIdx.x * blockDim.x + threadIdx.x) >> 5;
    int lane = threadIdx.x & 31;
    if (w >= BTH * Nn) return;
    int bth = w >> 10;
    int head = bth & (Hh - 1);
    const float* row = g_ht + (size_t)w * Dd;
    const float* as = a + head * 2 * Dd;
    const float* at = as + Dd;
    float s = 0.f, t = 0.f;
#pragma unroll
    for (int c = lane; c < Dd; c += 32) {
        float v = row[c];
        s += v * __ldg(as + c);
        t += v * __ldg(at + c);
    }
#pragma unroll
    for (int o = 16; o; o >>= 1) {
        s += __shfl_xor_sync(0xffffffffu, s, o);
        t += __shfl_xor_sync(0xffffffffu, t, o);
    }
    if (lane == 0) {
        g_Es [w] = expf(s);
        g_Es2[w] = expf(SLOPE * s);
        g_Et [w] = expf(t);
        g_Et2[w] = expf(SLOPE * t);
    }
}

// ---------------------------------------------------------------------------
// Kernel 3: row normalizers Zinv. One warp per (bth, i) row.
// ---------------------------------------------------------------------------
__global__ void k_zrow(const int* __restrict__ adj) {
    int w = (blockIdx.x * blockDim.x + threadIdx.x) >> 5;
    int lane = threadIdx.x & 31;
    if (w >= BTH * Nn) return;
    int bth = w >> 10, i = w & (Nn - 1);
    float Ei = g_Es[w], Ei2 = g_Es2[w];
    const int* arow = adj + (size_t)i * Nn;
    const float* Ft  = g_Et  + (size_t)bth * Nn;
    const float* Ft2 = g_Et2 + (size_t)bth * Nn;
    float sum = 0.f;
#pragma unroll 4
    for (int j = lane; j < Nn; j += 32) {
        if (arow[j] > 0) {
            float p = Ei * Ft[j];
            sum += (p >= 1.f) ? p : Ei2 * Ft2[j];
        }
    }
#pragma unroll
    for (int o = 16; o; o >>= 1) sum += __shfl_xor_sync(0xffffffffu, sum, o);
    if (lane == 0) g_Zinv[w] = 1.0f / sum;
}

// ---------------------------------------------------------------------------
// Kernel 4: h' = softmax-weighted aggregation. GEMM with on-the-fly weights.
// grid (8 i-tiles, 64 bth), 256 threads, 128 rows x 128 d per CTA.
// ---------------------------------------------------------------------------
__global__ void __launch_bounds__(256, 2)
k_attn(const int* __restrict__ adj) {
    __shared__ float Ws[16][132];   // Ws[jj][row]
    __shared__ float Hs[16][128];   // Hs[jj][d]
    __shared__ float sE[128], sE2[128];

    const int bth = blockIdx.y;
    const int i0  = blockIdx.x * 128;
    const int tid = threadIdx.x;
    const int tx = tid & 15, ty = tid >> 4;

    const float* htb = g_ht + (size_t)bth * Nn * Dd;
    const float* Ft  = g_Et  + (size_t)bth * Nn;
    const float* Ft2 = g_Et2 + (size_t)bth * Nn;

    if (tid < 128) {
        sE [tid] = g_Es [bth * Nn + i0 + tid];
        sE2[tid] = g_Es2[bth * Nn + i0 + tid];
    }
    __syncthreads();

    unsigned long long acc[8][4];
#pragma unroll
    for (int i = 0; i < 8; i++)
#pragma unroll
        for (int j = 0; j < 4; j++) acc[i][j] = 0ull;

    for (int j0 = 0; j0 < Nn; j0 += 16) {
        // ht tile (16 j-rows x 128 d)
#pragma unroll
        for (int q = tid; q < 512; q += 256) {
            int r = q >> 5, c4 = q & 31;
            *(float4*)&Hs[r][c4 * 4] =
                *(const float4*)(htb + (size_t)(j0 + r) * Dd + c4 * 4);
        }
        // weight tile: 128 rows x 16 j
#pragma unroll
        for (int q = tid; q < 512; q += 256) {
            int r  = q >> 2;
            int c4 = (q & 3) * 4;
            int4 ad = *(const int4*)(adj + (size_t)(i0 + r) * Nn + j0 + c4);
            float Ei = sE[r], Ei2 = sE2[r];
            float4 f = *(const float4*)(Ft  + j0 + c4);
            float4 g = *(const float4*)(Ft2 + j0 + c4);
            float w0 = 0.f, w1 = 0.f, w2 = 0.f, w3 = 0.f;
            if (ad.x > 0) { float p = Ei * f.x; w0 = (p >= 1.f) ? p : Ei2 * g.x; }
            if (ad.y > 0) { float p = Ei * f.y; w1 = (p >= 1.f) ? p : Ei2 * g.y; }
            if (ad.z > 0) { float p = Ei * f.z; w2 = (p >= 1.f) ? p : Ei2 * g.z; }
            if (ad.w > 0) { float p = Ei * f.w; w3 = (p >= 1.f) ? p : Ei2 * g.w; }
            Ws[c4 + 0][r] = w0;
            Ws[c4 + 1][r] = w1;
            Ws[c4 + 2][r] = w2;
            Ws[c4 + 3][r] = w3;
        }
        __syncthreads();
#pragma unroll
        for (int k = 0; k < 16; k++) {
            float a8[8], b8[8];
            *(float4*)(a8)     = *(const float4*)&Ws[k][ty * 8];
            *(float4*)(a8 + 4) = *(const float4*)&Ws[k][ty * 8 + 4];
            *(float4*)(b8)     = *(const float4*)&Hs[k][tx * 8];
            *(float4*)(b8 + 4) = *(const float4*)&Hs[k][tx * 8 + 4];
            unsigned long long bd[4];
#pragma unroll
            for (int j = 0; j < 4; j++) bd[j] = pk2(b8[2 * j], b8[2 * j + 1]);
#pragma unroll
            for (int i = 0; i < 8; i++) {
                unsigned long long ad = dup2(a8[i]);
#pragma unroll
                for (int j = 0; j < 4; j++) ffma2(acc[i][j], ad, bd[j]);
            }
        }
        __syncthreads();
    }

    float* op = g_part + (size_t)bth * Nn * Dd;
#pragma unroll
    for (int i = 0; i < 8; i++) {
        int r = i0 + ty * 8 + i;
        float zi = g_Zinv[bth * Nn + r];
#pragma unroll
        for (int j = 0; j < 4; j += 2) {
            float2 lo = unpk2(acc[i][j]), hi = unpk2(acc[i][j + 1]);
            float4 v = make_float4(lo.x * zi, lo.y * zi, hi.x * zi, hi.y * zi);
            *(float4*)(op + (size_t)r * Dd + tx * 8 + j * 2) = v;
        }
    }
}

// ---------------------------------------------------------------------------
// Kernel 5: mean over b. g_part halves are exactly [t][h][n][d] contiguous.
// ---------------------------------------------------------------------------
__global__ void k_mean(float* __restrict__ out) {
    int idx = blockIdx.x * blockDim.x + threadIdx.x;   // float4 index
    const int total4 = (Tt * Hh * Nn * Dd) / 4;        // 1,048,576
    if (idx < total4) {
        float4 p0 = ((const float4*)g_part)[idx];
        float4 p1 = ((const float4*)g_part)[total4 + idx];
        float4 v = make_float4(0.5f * (p0.x + p1.x), 0.5f * (p0.y + p1.y),
                               0.5f * (p0.z + p1.z), 0.5f * (p0.w + p1.w));
        ((float4*)out)[idx] = v;
    }
}

// ---------------------------------------------------------------------------
extern "C" void kernel_launch(void* const* d_in, const int* in_sizes, int n_in,
                              void* d_out, int out_size) {
    const float* h   = (const float*)d_in[0];
    const int*   adj = (const int*)  d_in[1];
    const float* W   = (const float*)d_in[2];
    const float* a   = (const float*)d_in[3];
    float* out = (float*)d_out;

    k_gemm_ht<<<dim3(8, 8, 8), 256>>>(h, W);
    k_edge<<<(BTH * Nn * 32) / 256, 256>>>(a);
    k_zrow<<<(BTH * Nn * 32) / 256, 256>>>(adj);
    k_attn<<<dim3(8, BTH), 256>>>(adj);
    k_mean<<<(Tt * Hh * Nn * Dd) / 4 / 256, 256>>>(out);
}

// round 8
// speedup vs baseline: 1.1185x; 1.1185x over previous
#include <cuda_runtime.h>
#include <cstdint>

// Problem constants
#define Bb 2
#define Tt 4
#define Nn 1024
#define Fin 256
#define Hh 8
#define Dd 128
#define BTH (Bb*Tt*Hh)          // 64
#define SLOPE 0.2f

// Scratch (device globals; no runtime allocation allowed)
__device__ float g_ht[(size_t)BTH * Nn * Dd];     // 32 MB, [bth][n][d]
__device__ float g_part[(size_t)BTH * Nn * Dd];   // 32 MB partial outputs
__device__ float g_Es [BTH * Nn];                 // exp(src)
__device__ float g_Es2[BTH * Nn];                 // exp(0.2*src)
__device__ float g_Et [BTH * Nn];                 // exp(tgt)
__device__ float g_Et2[BTH * Nn];                 // exp(0.2*tgt)
__device__ float g_Zinv[BTH * Nn];                // 1 / row-sum of weights

// ---- packed f32x2 helpers (family-wide PTX, sm_100+) ----------------------
__device__ __forceinline__ void ffma2(unsigned long long& d,
                                      unsigned long long a,
                                      unsigned long long b) {
    asm("fma.rn.f32x2 %0, %1, %2, %0;" : "+l"(d) : "l"(a), "l"(b));
}
__device__ __forceinline__ unsigned long long pk2(float lo, float hi) {
    unsigned long long r;
    asm("mov.b64 %0, {%1, %2};" : "=l"(r) : "f"(lo), "f"(hi));
    return r;
}
__device__ __forceinline__ unsigned long long dup2(float v) {
    unsigned long long r;
    asm("mov.b64 %0, {%1, %1};" : "=l"(r) : "f"(v));
    return r;
}
__device__ __forceinline__ float2 unpk2(unsigned long long u) {
    union { unsigned long long u; float2 f; } c; c.u = u; return c.f;
}

// ---------------------------------------------------------------------------
// Kernel 1: ht = h @ W, written as [bt][head][n][d]
// grid (8 heads, 8 row-tiles, 8 bt), 256 threads, 128x128x16 tiles.
// B columns per thread: {tx*4..+3} and {64+tx*4..+3}  (conflict-free LDS)
// ---------------------------------------------------------------------------
__global__ void __launch_bounds__(256, 2)
k_gemm_ht(const float* __restrict__ h, const float* __restrict__ W) {
    __shared__ float As[16][132];   // As[k][row]
    __shared__ float Bs[16][128];   // Bs[k][col]

    const int bt   = blockIdx.z;
    const int head = blockIdx.x;
    const int row0 = blockIdx.y * 128;
    const int col0 = head * 128;

    const float* A = h + (size_t)bt * Nn * Fin;   // [1024][256]
    const int tid = threadIdx.x;
    const int tx = tid & 15, ty = tid >> 4;

    unsigned long long acc[8][4];
#pragma unroll
    for (int i = 0; i < 8; i++)
#pragma unroll
        for (int j = 0; j < 4; j++) acc[i][j] = 0ull;

    for (int kt = 0; kt < Fin; kt += 16) {
#pragma unroll
        for (int q = tid; q < 512; q += 256) {
            int r = q >> 2, c4 = q & 3;
            float4 v = *(const float4*)(A + (size_t)(row0 + r) * Fin + kt + c4 * 4);
            As[c4 * 4 + 0][r] = v.x;
            As[c4 * 4 + 1][r] = v.y;
            As[c4 * 4 + 2][r] = v.z;
            As[c4 * 4 + 3][r] = v.w;
        }
#pragma unroll
        for (int q = tid; q < 512; q += 256) {
            int r = q >> 5, c4 = q & 31;
            *(float4*)&Bs[r][c4 * 4] =
                *(const float4*)(W + (size_t)(kt + r) * (Hh * Dd) + col0 + c4 * 4);
        }
        __syncthreads();
#pragma unroll
        for (int k = 0; k < 16; k++) {
            float a8[8], b8[8];
            *(float4*)(a8)     = *(const float4*)&As[k][ty * 8];
            *(float4*)(a8 + 4) = *(const float4*)&As[k][ty * 8 + 4];
            *(float4*)(b8)     = *(const float4*)&Bs[k][tx * 4];        // contiguous
            *(float4*)(b8 + 4) = *(const float4*)&Bs[k][64 + tx * 4];   // contiguous
            unsigned long long bd[4];
#pragma unroll
            for (int j = 0; j < 4; j++) bd[j] = pk2(b8[2 * j], b8[2 * j + 1]);
#pragma unroll
            for (int i = 0; i < 8; i++) {
                unsigned long long ad = dup2(a8[i]);
#pragma unroll
                for (int j = 0; j < 4; j++) ffma2(acc[i][j], ad, bd[j]);
            }
        }
        __syncthreads();
    }

    float* outp = g_ht + (size_t)(bt * Hh + head) * Nn * Dd;
#pragma unroll
    for (int i = 0; i < 8; i++) {
        int r = row0 + ty * 8 + i;
        float2 l0 = unpk2(acc[i][0]), h0 = unpk2(acc[i][1]);
        float2 l1 = unpk2(acc[i][2]), h1 = unpk2(acc[i][3]);
        *(float4*)(outp + (size_t)r * Dd + tx * 4) =
            make_float4(l0.x, l0.y, h0.x, h0.y);
        *(float4*)(outp + (size_t)r * Dd + 64 + tx * 4) =
            make_float4(l1.x, l1.y, h1.x, h1.y);
    }
}

// ---------------------------------------------------------------------------
// Kernel 2: per-node src/tgt dot products and the 4 exps. One warp per node.
// ---------------------------------------------------------------------------
__global__ void k_edge(const float* __restrict__ a) {
    int w = (blockIdx.x * blockDim.x + threadIdx.x) >> 5;
    int lane = threadIdx.x & 31;
    if (w >= BTH * Nn) return;
    int bth = w >> 10;
    int head = bth & (Hh - 1);
    const float* row = g_ht + (size_t)w * Dd;
    const float* as = a + head * 2 * Dd;
    const float* at = as + Dd;
    float s = 0.f, t = 0.f;
#pragma unroll
    for (int c = lane; c < Dd; c += 32) {
        float v = row[c];
        s += v * __ldg(as + c);
        t += v * __ldg(at + c);
    }
#pragma unroll
    for (int o = 16; o; o >>= 1) {
        s += __shfl_xor_sync(0xffffffffu, s, o);
        t += __shfl_xor_sync(0xffffffffu, t, o);
    }
    if (lane == 0) {
        g_Es [w] = expf(s);
        g_Es2[w] = expf(SLOPE * s);
        g_Et [w] = expf(t);
        g_Et2[w] = expf(SLOPE * t);
    }
}

// ---------------------------------------------------------------------------
// Kernel 3: row normalizers Zinv. One warp per (bth, i) row.
// ---------------------------------------------------------------------------
__global__ void k_zrow(const int* __restrict__ adj) {
    int w = (blockIdx.x * blockDim.x + threadIdx.x) >> 5;
    int lane = threadIdx.x & 31;
    if (w >= BTH * Nn) return;
    int bth = w >> 10, i = w & (Nn - 1);
    float Ei = g_Es[w], Ei2 = g_Es2[w];
    const int* arow = adj + (size_t)i * Nn;
    const float* Ft  = g_Et  + (size_t)bth * Nn;
    const float* Ft2 = g_Et2 + (size_t)bth * Nn;
    float sum = 0.f;
#pragma unroll 4
    for (int j = lane; j < Nn; j += 32) {
        if (arow[j] > 0) {
            float p = Ei * Ft[j];
            sum += (p >= 1.f) ? p : Ei2 * Ft2[j];
        }
    }
#pragma unroll
    for (int o = 16; o; o >>= 1) sum += __shfl_xor_sync(0xffffffffu, sum, o);
    if (lane == 0) g_Zinv[w] = 1.0f / sum;
}

// ---------------------------------------------------------------------------
// Kernel 4: h' = softmax-weighted aggregation. GEMM with on-the-fly weights.
// grid (8 i-tiles, 64 bth), 256 threads, 128 rows x 128 d per CTA.
// B columns per thread: {tx*4..+3} and {64+tx*4..+3}  (conflict-free LDS)
// ---------------------------------------------------------------------------
__global__ void __launch_bounds__(256, 2)
k_attn(const int* __restrict__ adj) {
    __shared__ float Ws[16][132];   // Ws[jj][row]
    __shared__ float Hs[16][128];   // Hs[jj][d]
    __shared__ float sE[128], sE2[128];

    const int bth = blockIdx.y;
    const int i0  = blockIdx.x * 128;
    const int tid = threadIdx.x;
    const int tx = tid & 15, ty = tid >> 4;

    const float* htb = g_ht + (size_t)bth * Nn * Dd;
    const float* Ft  = g_Et  + (size_t)bth * Nn;
    const float* Ft2 = g_Et2 + (size_t)bth * Nn;

    if (tid < 128) {
        sE [tid] = g_Es [bth * Nn + i0 + tid];
        sE2[tid] = g_Es2[bth * Nn + i0 + tid];
    }
    __syncthreads();

    unsigned long long acc[8][4];
#pragma unroll
    for (int i = 0; i < 8; i++)
#pragma unroll
        for (int j = 0; j < 4; j++) acc[i][j] = 0ull;

    for (int j0 = 0; j0 < Nn; j0 += 16) {
        // ht tile (16 j-rows x 128 d)
#pragma unroll
        for (int q = tid; q < 512; q += 256) {
            int r = q >> 5, c4 = q & 31;
            *(float4*)&Hs[r][c4 * 4] =
                *(const float4*)(htb + (size_t)(j0 + r) * Dd + c4 * 4);
        }
        // weight tile: 128 rows x 16 j
#pragma unroll
        for (int q = tid; q < 512; q += 256) {
            int r  = q >> 2;
            int c4 = (q & 3) * 4;
            int4 ad = *(const int4*)(adj + (size_t)(i0 + r) * Nn + j0 + c4);
            float Ei = sE[r], Ei2 = sE2[r];
            float4 f = *(const float4*)(Ft  + j0 + c4);
            float4 g = *(const float4*)(Ft2 + j0 + c4);
            float w0 = 0.f, w1 = 0.f, w2 = 0.f, w3 = 0.f;
            if (ad.x > 0) { float p = Ei * f.x; w0 = (p >= 1.f) ? p : Ei2 * g.x; }
            if (ad.y > 0) { float p = Ei * f.y; w1 = (p >= 1.f) ? p : Ei2 * g.y; }
            if (ad.z > 0) { float p = Ei * f.z; w2 = (p >= 1.f) ? p : Ei2 * g.z; }
            if (ad.w > 0) { float p = Ei * f.w; w3 = (p >= 1.f) ? p : Ei2 * g.w; }
            Ws[c4 + 0][r] = w0;
            Ws[c4 + 1][r] = w1;
            Ws[c4 + 2][r] = w2;
            Ws[c4 + 3][r] = w3;
        }
        __syncthreads();
#pragma unroll
        for (int k = 0; k < 16; k++) {
            float a8[8], b8[8];
            *(float4*)(a8)     = *(const float4*)&Ws[k][ty * 8];
            *(float4*)(a8 + 4) = *(const float4*)&Ws[k][ty * 8 + 4];
            *(float4*)(b8)     = *(const float4*)&Hs[k][tx * 4];        // contiguous
            *(float4*)(b8 + 4) = *(const float4*)&Hs[k][64 + tx * 4];   // contiguous
            unsigned long long bd[4];
#pragma unroll
            for (int j = 0; j < 4; j++) bd[j] = pk2(b8[2 * j], b8[2 * j + 1]);
#pragma unroll
            for (int i = 0; i < 8; i++) {
                unsigned long long ad = dup2(a8[i]);
#pragma unroll
                for (int j = 0; j < 4; j++) ffma2(acc[i][j], ad, bd[j]);
            }
        }
        __syncthreads();
    }

    float* op = g_part + (size_t)bth * Nn * Dd;
#pragma unroll
    for (int i = 0; i < 8; i++) {
        int r = i0 + ty * 8 + i;
        float zi = g_Zinv[bth * Nn + r];
        float2 l0 = unpk2(acc[i][0]), h0 = unpk2(acc[i][1]);
        float2 l1 = unpk2(acc[i][2]), h1 = unpk2(acc[i][3]);
        *(float4*)(op + (size_t)r * Dd + tx * 4) =
            make_float4(l0.x * zi, l0.y * zi, h0.x * zi, h0.y * zi);
        *(float4*)(op + (size_t)r * Dd + 64 + tx * 4) =
            make_float4(l1.x * zi, l1.y * zi, h1.x * zi, h1.y * zi);
    }
}

// ---------------------------------------------------------------------------
// Kernel 5: mean over b. g_part halves are exactly [t][h][n][d] contiguous.
// ---------------------------------------------------------------------------
__global__ void k_mean(float* __restrict__ out) {
    int idx = blockIdx.x * blockDim.x + threadIdx.x;   // float4 index
    const int total4 = (Tt * Hh * Nn * Dd) / 4;        // 1,048,576
    if (idx < total4) {
        float4 p0 = ((const float4*)g_part)[idx];
        float4 p1 = ((const float4*)g_part)[total4 + idx];
        float4 v = make_float4(0.5f * (p0.x + p1.x), 0.5f * (p0.y + p1.y),
                               0.5f * (p0.z + p1.z), 0.5f * (p0.w + p1.w));
        ((float4*)out)[idx] = v;
    }
}

// ---------------------------------------------------------------------------
extern "C" void kernel_launch(void* const* d_in, const int* in_sizes, int n_in,
                              void* d_out, int out_size) {
    const float* h   = (const float*)d_in[0];
    const int*   adj = (const int*)  d_in[1];
    const float* W   = (const float*)d_in[2];
    const float* a   = (const float*)d_in[3];
    float* out = (float*)d_out;

    k_gemm_ht<<<dim3(8, 8, 8), 256>>>(h, W);
    k_edge<<<(BTH * Nn * 32) / 256, 256>>>(a);
    k_zrow<<<(BTH * Nn * 32) / 256, 256>>>(adj);
    k_attn<<<dim3(8, BTH), 256>>>(adj);
    k_mean<<<(Tt * Hh * Nn * Dd) / 4 / 256, 256>>>(out);
}